// round 4
// baseline (speedup 1.0000x reference)
#include <cuda_runtime.h>
#include <stdint.h>

// Fp8Unpadding: gather un-padded rows out of a 256-row-padded concatenation.
// M_SPLITS = {1000,2300,512,3777,129,2048,900,1500}, HIDDEN=4096 (f32).
//
// R4: the gather is exactly 6 contiguous segment copies (groups with equal
// row-delta merge: 2/3 and 5/6). Route them through the copy engines via
// cudaMemcpyAsync D2D (graph-capturable, allowed by harness). Hypothesis:
// CE burst scheduling beats the SM path's ~78% mixed-stream HBM ceiling.
//
// padded offsets: 0,1024,3328,3840,7680,7936,9984,11008
// dst offsets:    0,1000,3300,3812,7589,7718,9766,10666
// deltas:         0,  24,  28,  28,  91, 218, 218, 342

static constexpr size_t ROW_BYTES = 4096 * sizeof(float);  // 16 KB

struct Seg { long src_row; long dst_row; long rows; };

static constexpr Seg SEGS[6] = {
    {    0,     0, 1000},   // g0
    { 1024,  1000, 2300},   // g1
    { 3328,  3300, 4289},   // g2+g3 (delta 28)
    { 7680,  7589,  129},   // g4
    { 7936,  7718, 2948},   // g5+g6 (delta 218)
    {11008, 10666, 1500},   // g7
};

extern "C" void kernel_launch(void* const* d_in, const int* in_sizes, int n_in,
                              void* d_out, int out_size)
{
    const char* in  = (const char*)d_in[0];   // f32 [12544, 4096]
    char*       out = (char*)d_out;           // f32 [12166, 4096]

    for (int s = 0; s < 6; s++) {
        cudaMemcpyAsync(out + (size_t)SEGS[s].dst_row * ROW_BYTES,
                        in  + (size_t)SEGS[s].src_row * ROW_BYTES,
                        (size_t)SEGS[s].rows * ROW_BYTES,
                        cudaMemcpyDeviceToDevice, 0);
    }
}

// round 5
// speedup vs baseline: 1.2022x; 1.2022x over previous
#include <cuda_runtime.h>
#include <stdint.h>

// Fp8Unpadding: gather un-padded rows out of a 256-row-padded concatenation.
// M_SPLITS = {1000,2300,512,3777,129,2048,900,1500}, HIDDEN=4096 (f32).
// dst row r maps to src row r + DELTA[group(r)]; DELTA constant per group.
//
// Row boundaries (cumulative m):  1000, 3300, 3812, 7589, 7718, 9766, 10666, 12166
// Row deltas:                        0,   24,   28,   28,   91,  218,   218,   342
//
// R5: back to the R2 winner (one-shot 6083 CTAs, 8x float4/thread, MLP=8,
// streaming hints), with the row-delta hoisted to block-uniform: each block
// covers exactly 2 rows (2048 float4 = 2 x 1024), so only 2 delta lookups
// per block, computed from blockIdx (uniform-register friendly).

static constexpr int HIDDEN_V4  = 4096 / 4;                 // 1024
static constexpr int TOTAL_ROWS = 12166;
static constexpr int TOTAL_V4   = TOTAL_ROWS * HIDDEN_V4;   // 12,457,984
static constexpr int UNROLL     = 8;
static constexpr int TPB        = 256;
static constexpr int PER_BLOCK  = TPB * UNROLL;             // 2048 = 2 rows
static constexpr int NBLOCKS    = TOTAL_V4 / PER_BLOCK;     // 6083 (exact)

__device__ __forceinline__ int row_delta(int row)
{
    return (row < 1000)  ? 0
         : (row < 3300)  ? 24
         : (row < 7589)  ? 28
         : (row < 7718)  ? 91
         : (row < 10666) ? 218
         :                 342;
}

__global__ void __launch_bounds__(TPB)
unpad_gather_kernel(const float4* __restrict__ in, float4* __restrict__ out)
{
    int row0 = blockIdx.x * 2;                 // block covers rows row0, row0+1
    int d0 = row_delta(row0) * HIDDEN_V4;      // block-uniform
    int d1 = row_delta(row0 + 1) * HIDDEN_V4;  // block-uniform

    int base = blockIdx.x * PER_BLOCK + threadIdx.x;

    float4 v[UNROLL];

    // front-batched independent loads (deep MLP); j<4 -> row0, j>=4 -> row1
    #pragma unroll
    for (int j = 0; j < UNROLL; j++) {
        int i = base + j * TPB;
        v[j] = __ldcs(in + i + (j < 4 ? d0 : d1));
    }

    #pragma unroll
    for (int j = 0; j < UNROLL; j++) {
        __stcs(out + base + j * TPB, v[j]);
    }
}

extern "C" void kernel_launch(void* const* d_in, const int* in_sizes, int n_in,
                              void* d_out, int out_size)
{
    const float4* in  = (const float4*)d_in[0];   // f32 [12544, 4096]
    float4*       out = (float4*)d_out;           // f32 [12166, 4096]

    unpad_gather_kernel<<<NBLOCKS, TPB>>>(in, out);
}

// round 6
// speedup vs baseline: 1.2078x; 1.0047x over previous
#include <cuda_runtime.h>
#include <stdint.h>

// Fp8Unpadding: gather un-padded rows out of a 256-row-padded concatenation.
// M_SPLITS = {1000,2300,512,3777,129,2048,900,1500}, HIDDEN=4096 (f32).
// dst row r maps to src row r + DELTA[group(r)]; DELTA constant per group.
//
// Row boundaries (cumulative m):  1000, 3300, 3812, 7589, 7718, 9766, 10666, 12166
// Row deltas:                        0,   24,   28,   28,   91,  218,   218,   342
//
// R6: one 16KB row per block. TPB=128, 8x float4 per thread = 1024 v4 = 1 row.
// Single block-uniform delta, front-batched loads (MLP=8), streaming hints.
// Smaller CTA -> up to 12 CTAs/SM at regs~40 (occ ~75% vs 61.6%).

static constexpr int HIDDEN_V4  = 4096 / 4;   // 1024 float4 per row
static constexpr int TOTAL_ROWS = 12166;
static constexpr int UNROLL     = 8;
static constexpr int TPB        = 128;        // TPB * UNROLL = 1024 = 1 row

__device__ __forceinline__ int row_delta(int row)
{
    return (row < 1000)  ? 0
         : (row < 3300)  ? 24
         : (row < 7589)  ? 28
         : (row < 7718)  ? 91
         : (row < 10666) ? 218
         :                 342;
}

__global__ void __launch_bounds__(TPB)
unpad_gather_kernel(const float4* __restrict__ in, float4* __restrict__ out)
{
    int row = blockIdx.x;                        // one row per block
    const float4* __restrict__ src = in  + (row + row_delta(row)) * HIDDEN_V4;
    float4*       __restrict__ dst = out + row * HIDDEN_V4;

    float4 v[UNROLL];

    // front-batched independent loads (deep MLP)
    #pragma unroll
    for (int j = 0; j < UNROLL; j++)
        v[j] = __ldcs(src + j * TPB + threadIdx.x);

    #pragma unroll
    for (int j = 0; j < UNROLL; j++)
        __stcs(dst + j * TPB + threadIdx.x, v[j]);
}

extern "C" void kernel_launch(void* const* d_in, const int* in_sizes, int n_in,
                              void* d_out, int out_size)
{
    const float4* in  = (const float4*)d_in[0];   // f32 [12544, 4096]
    float4*       out = (float4*)d_out;           // f32 [12166, 4096]

    unpad_gather_kernel<<<TOTAL_ROWS, TPB>>>(in, out);
}